// round 5
// baseline (speedup 1.0000x reference)
#include <cuda_runtime.h>
#include <cstdint>

#define B_SIZE 131072
#define NAG 8
#define HXS 64
#define ENC 128
#define ACTS 5
#define TILE 128

// scratch (device globals: no allocation allowed)
__device__ float g_comm[NAG * HXS];
__device__ float g_pre2[NAG * HXS];

__device__ __forceinline__ uint32_t f2tf(float f) {
    uint32_t r; asm("cvt.rna.tf32.f32 %0, %1;" : "=r"(r) : "f"(f)); return r;
}
__device__ __forceinline__ void split_tf(float v, uint32_t &hi, uint32_t &lo) {
    hi = f2tf(v);
    lo = f2tf(v - __uint_as_float(hi));
}
__device__ __forceinline__ void mma_tf32(float* d, uint32_t a0, uint32_t a1,
                                         uint32_t a2, uint32_t a3,
                                         uint32_t b0, uint32_t b1) {
    asm volatile(
        "mma.sync.aligned.m16n8k8.row.col.f32.tf32.tf32.f32 "
        "{%0,%1,%2,%3}, {%4,%5,%6,%7}, {%8,%9}, {%0,%1,%2,%3};"
        : "+f"(d[0]), "+f"(d[1]), "+f"(d[2]), "+f"(d[3])
        : "r"(a0), "r"(a1), "r"(a2), "r"(a3), "r"(b0), "r"(b1));
}
__device__ __forceinline__ float fast_tanh(float x) {
    float r; asm("tanh.approx.f32 %0, %1;" : "=f"(r) : "f"(x)); return r;
}

__global__ void k_zero() {
    if (threadIdx.x < NAG * HXS) g_comm[threadIdx.x] = 0.f;
}

// ---------------------------------------------------------------------------
// Shared smem layout (floats) for the encoder portion (both kernels):
//   sA   [128][132] fp32 h1 tile, aliased later as sH [128][68] fp32 h tile
//   sWH  [128][72]  tf32-hi of W2 (kernel B later aliases first 64 rows = Wc hi)
//   sWL  [128][72]  tf32-lo
//   sObs [128][16], sW1[256], sb1[128], sb2[64]
// ---------------------------------------------------------------------------
#define E_SA   0
#define E_SWH  16896
#define E_SWL  26112
#define E_SOBS 35328
#define E_SW1  37376
#define E_SB1  37632
#define E_SB2  37760
#define E_END  37824
// kernel A extras
#define A_SC   E_END           // [8][132]
#define A_TOTF (E_END + 1056)  // 38880 floats = 155,520 B
// kernel B extras
#define B_SWD  E_END           // [64*5]
#define B_SP   (E_END + 320)   // [64]
#define B_SBD  (E_END + 384)   // [8]
#define B_TOTF (E_END + 392)   // 38216 floats = 152,864 B

// Encoder tile: h = relu(relu(obs@W1+b1)@W2+b2) in tf32x3.
// On exit: h in sH (stride 68), all threads synced.
__device__ __forceinline__ void encoder_tile(
    float* sm, int n, int tid, int b0,
    const float* __restrict__ obs, const float* __restrict__ W1,
    const float* __restrict__ b1, const float* __restrict__ W2,
    const float* __restrict__ b2)
{
    float* sA   = sm + E_SA;
    uint32_t* sWH = (uint32_t*)(sm + E_SWH);
    uint32_t* sWL = (uint32_t*)(sm + E_SWL);
    float* sObs = sm + E_SOBS;
    float* sW1  = sm + E_SW1;
    float* sb1  = sm + E_SB1;
    float* sb2  = sm + E_SB2;
    float* sH   = sm + E_SA;   // alias

    // stage inputs
    {
        const float4* src = (const float4*)(obs + (size_t)b0 * 16);
        float4* dst = (float4*)sObs;
        dst[tid]       = src[tid];
        dst[tid + 256] = src[tid + 256];
    }
    sW1[tid] = W1[n * 256 + tid];
    if (tid < 128) sb1[tid] = b1[n * 128 + tid];
    if (tid < 64)  sb2[tid] = b2[n * 64 + tid];
    for (int i = tid; i < ENC * HXS; i += 256) {
        int r = i >> 6, c = i & 63;
        uint32_t hi, lo;
        split_tf(W2[n * ENC * HXS + i], hi, lo);
        sWH[r * 72 + c] = hi;
        sWL[r * 72 + c] = lo;
    }
    __syncthreads();

    // Phase A: h1 = relu(obs @ W1 + b1) -> sA fp32
    {
        const int col = tid & 127;
        const int rb  = (tid >> 7) * 64;
        const float w0 = sW1[col], w1 = sW1[128 + col], bb = sb1[col];
#pragma unroll 8
        for (int j = 0; j < 64; j++) {
            int r = rb + j;
            float o0 = sObs[r * 16 + 2 * n];
            float o1 = sObs[r * 16 + 2 * n + 1];
            sA[r * 132 + col] = fmaxf(fmaf(o0, w0, fmaf(o1, w1, bb)), 0.f);
        }
    }
    __syncthreads();

    // MMA x3: [128 x 128] @ [128 x 64]
    const int w = tid >> 5, lane = tid & 31, g = lane >> 2, t = lane & 3;
    const int ar = w * 16 + g;
    float acc[8][4];
#pragma unroll
    for (int nt = 0; nt < 8; nt++)
#pragma unroll
        for (int e = 0; e < 4; e++) acc[nt][e] = 0.f;

#pragma unroll
    for (int k = 0; k < 16; k++) {
        uint32_t ah0, al0, ah1, al1, ah2, al2, ah3, al3;
        split_tf(sA[ar * 132 + k * 8 + t],           ah0, al0);
        split_tf(sA[(ar + 8) * 132 + k * 8 + t],     ah1, al1);
        split_tf(sA[ar * 132 + k * 8 + t + 4],       ah2, al2);
        split_tf(sA[(ar + 8) * 132 + k * 8 + t + 4], ah3, al3);
#pragma unroll
        for (int nt = 0; nt < 8; nt++) {
            uint32_t bh0 = sWH[(k * 8 + t) * 72 + nt * 8 + g];
            uint32_t bh1 = sWH[(k * 8 + t + 4) * 72 + nt * 8 + g];
            uint32_t bl0 = sWL[(k * 8 + t) * 72 + nt * 8 + g];
            uint32_t bl1 = sWL[(k * 8 + t + 4) * 72 + nt * 8 + g];
            mma_tf32(acc[nt], ah0, ah1, ah2, ah3, bh0, bh1);
            mma_tf32(acc[nt], al0, al1, al2, al3, bh0, bh1);
            mma_tf32(acc[nt], ah0, ah1, ah2, ah3, bl0, bl1);
        }
    }
    __syncthreads();   // all warps done reading sA

    // epilogue: h = relu(acc + b2) -> sH (alias of sA)
#pragma unroll
    for (int nt = 0; nt < 8; nt++) {
        int c0 = nt * 8 + 2 * t;
        float p0 = sb2[c0], p1 = sb2[c0 + 1];
        sH[ar * 68 + c0]           = fmaxf(acc[nt][0] + p0, 0.f);
        sH[ar * 68 + c0 + 1]       = fmaxf(acc[nt][1] + p1, 0.f);
        sH[(ar + 8) * 68 + c0]     = fmaxf(acc[nt][2] + p0, 0.f);
        sH[(ar + 8) * 68 + c0 + 1] = fmaxf(acc[nt][3] + p1, 0.f);
    }
    __syncthreads();
}

// ---------------------------------------------------------------------------
// Kernel A: encoder + comm partial accumulation (no h store)
// ---------------------------------------------------------------------------
__global__ __launch_bounds__(256) void k_comm(
    const float* __restrict__ obs, const float* __restrict__ W1,
    const float* __restrict__ b1, const float* __restrict__ W2,
    const float* __restrict__ b2)
{
    extern __shared__ float sm[];
    const int n   = blockIdx.y;
    const int tid = threadIdx.x;
    const int b0  = blockIdx.x * TILE;

    encoder_tile(sm, n, tid, b0, obs, W1, b1, W2, b2);

    float* sH   = sm + E_SA;     // stride 68
    float* sObs = sm + E_SOBS;
    float* sC   = sm + A_SC;     // [8][132]

    // comm coefficients: coef_i = mask[i][n] / J[i]
    if (tid < 128) {
        float px[NAG], py[NAG];
#pragma unroll
        for (int j = 0; j < NAG; j++) {
            px[j] = sObs[tid * 16 + 2 * j] * 2.0f;       // GRID[0]-1
            py[j] = sObs[tid * 16 + 2 * j + 1] * 6.0f;   // GRID[1]-1
        }
#pragma unroll
        for (int i = 0; i < NAG; i++) {
            float J = 0.f, mn = 0.f;
#pragma unroll
            for (int j = 0; j < NAG; j++) {
                float d = fabsf(px[i] - px[j]) + fabsf(py[i] - py[j]);
                bool msk = (d > 0.f) && (d < 2.0f);
                J += msk ? 1.f : 0.f;
                if (j == n) mn = msk ? 1.f : 0.f;
            }
            if (J <= 0.f) J = 1.f;
            sC[i * 132 + tid] = mn / J;
        }
    }
    __syncthreads();

    // per-block 8x64 reduction: partial[i][o] = sum_bb coef[i][bb]*h[bb][o]
    const int o = tid & 63, i0 = tid >> 6;
    float s0 = 0.f, s1 = 0.f;
#pragma unroll 4
    for (int bb = 0; bb < TILE; bb++) {
        float hv = sH[bb * 68 + o];
        s0 = fmaf(sC[i0 * 132 + bb], hv, s0);
        s1 = fmaf(sC[(i0 + 4) * 132 + bb], hv, s1);
    }
    atomicAdd(&g_comm[i0 * 64 + o], s0);
    atomicAdd(&g_comm[(i0 + 4) * 64 + o], s1);
}

// pre2[n][o] = bc[n][o] + sum_h comm[n][h] * Wc[n][HX+h][o]
__global__ void k_pre(const float* __restrict__ Wc, const float* __restrict__ bc) {
    const int n = blockIdx.x, o = threadIdx.x;
    float s = bc[n * HXS + o];
#pragma unroll 8
    for (int h = 0; h < HXS; h++)
        s = fmaf(g_comm[n * HXS + h], Wc[n * 2 * HXS * HXS + (HXS + h) * HXS + o], s);
    g_pre2[n * HXS + o] = s;
}

// ---------------------------------------------------------------------------
// Kernel B: encoder (recompute) + decoder, all fused
// ---------------------------------------------------------------------------
__global__ __launch_bounds__(256) void k_main(
    const float* __restrict__ obs, const float* __restrict__ W1,
    const float* __restrict__ b1, const float* __restrict__ W2,
    const float* __restrict__ b2, const float* __restrict__ Wc,
    const float* __restrict__ Wd, const float* __restrict__ bd,
    float* __restrict__ out)
{
    extern __shared__ float sm[];
    const int n   = blockIdx.y;
    const int tid = threadIdx.x;
    const int b0  = blockIdx.x * TILE;

    encoder_tile(sm, n, tid, b0, obs, W1, b1, W2, b2);
    // h now in sH (stride 68); sWH/sWL free for reuse.

    float* sH  = sm + E_SA;
    uint32_t* sBH = (uint32_t*)(sm + E_SWH);   // Wc_low hi, [64][72]
    uint32_t* sBL = (uint32_t*)(sm + E_SWL);   // Wc_low lo
    float* sWd = sm + B_SWD;
    float* sP  = sm + B_SP;
    float* sbd = sm + B_SBD;

    // load decoder weights (Wc lower half: rows 0..63 of [2*HX][HX])
    for (int i = tid; i < HXS * HXS; i += 256) {
        int r = i >> 6, c = i & 63;
        uint32_t hi, lo;
        split_tf(Wc[n * 2 * HXS * HXS + i], hi, lo);
        sBH[r * 72 + c] = hi;
        sBL[r * 72 + c] = lo;
    }
    for (int i = tid; i < HXS * ACTS; i += 256) sWd[i] = Wd[n * HXS * ACTS + i];
    if (tid < 64) sP[tid] = g_pre2[n * 64 + tid];
    if (tid < 5)  sbd[tid] = bd[n * 5 + tid];
    __syncthreads();

    // MMA x3: [128 x 64] @ [64 x 64]
    const int w = tid >> 5, lane = tid & 31, g = lane >> 2, t = lane & 3;
    const int ar = w * 16 + g;
    float acc[8][4];
#pragma unroll
    for (int nt = 0; nt < 8; nt++)
#pragma unroll
        for (int e = 0; e < 4; e++) acc[nt][e] = 0.f;

#pragma unroll
    for (int k = 0; k < 8; k++) {
        uint32_t ah0, al0, ah1, al1, ah2, al2, ah3, al3;
        split_tf(sH[ar * 68 + k * 8 + t],           ah0, al0);
        split_tf(sH[(ar + 8) * 68 + k * 8 + t],     ah1, al1);
        split_tf(sH[ar * 68 + k * 8 + t + 4],       ah2, al2);
        split_tf(sH[(ar + 8) * 68 + k * 8 + t + 4], ah3, al3);
#pragma unroll
        for (int nt = 0; nt < 8; nt++) {
            uint32_t bh0 = sBH[(k * 8 + t) * 72 + nt * 8 + g];
            uint32_t bh1 = sBH[(k * 8 + t + 4) * 72 + nt * 8 + g];
            uint32_t bl0 = sBL[(k * 8 + t) * 72 + nt * 8 + g];
            uint32_t bl1 = sBL[(k * 8 + t + 4) * 72 + nt * 8 + g];
            mma_tf32(acc[nt], ah0, ah1, ah2, ah3, bh0, bh1);
            mma_tf32(acc[nt], al0, al1, al2, al3, bh0, bh1);
            mma_tf32(acc[nt], ah0, ah1, ah2, ah3, bl0, bl1);
        }
    }
    __syncthreads();   // all warps done reading sH

    // epilogue: h2 = tanh(acc + pre2) -> sH (reuse region)
#pragma unroll
    for (int nt = 0; nt < 8; nt++) {
        int c0 = nt * 8 + 2 * t;
        float p0 = sP[c0], p1 = sP[c0 + 1];
        sH[ar * 68 + c0]           = fast_tanh(acc[nt][0] + p0);
        sH[ar * 68 + c0 + 1]       = fast_tanh(acc[nt][1] + p1);
        sH[(ar + 8) * 68 + c0]     = fast_tanh(acc[nt][2] + p0);
        sH[(ar + 8) * 68 + c0 + 1] = fast_tanh(acc[nt][3] + p1);
    }
    __syncthreads();

    // q = h2 @ Wd + bd, one batch row per thread (tid < 128)
    if (tid < 128) {
        float q0 = sbd[0], q1 = sbd[1], q2 = sbd[2], q3 = sbd[3], q4 = sbd[4];
        const float* hr = sH + tid * 68;
#pragma unroll
        for (int j = 0; j < 64; j++) {
            float hv = hr[j];
            const float* wd = sWd + j * 5;
            q0 = fmaf(hv, wd[0], q0);
            q1 = fmaf(hv, wd[1], q1);
            q2 = fmaf(hv, wd[2], q2);
            q3 = fmaf(hv, wd[3], q3);
            q4 = fmaf(hv, wd[4], q4);
        }
        float* o = out + ((size_t)(b0 + tid) * NAG + n) * ACTS;
        o[0] = q0; o[1] = q1; o[2] = q2; o[3] = q3; o[4] = q4;
    }
}

extern "C" void kernel_launch(void* const* d_in, const int* in_sizes, int n_in,
                              void* d_out, int out_size)
{
    const float* obs = (const float*)d_in[0];
    const float* W1  = (const float*)d_in[1];
    const float* b1  = (const float*)d_in[2];
    const float* W2  = (const float*)d_in[3];
    const float* b2  = (const float*)d_in[4];
    const float* Wc  = (const float*)d_in[5];
    const float* bc  = (const float*)d_in[6];
    const float* Wd  = (const float*)d_in[7];
    const float* bd  = (const float*)d_in[8];
    float* out = (float*)d_out;

    const int SMEM_A = A_TOTF * sizeof(float);   // 155,520 B
    const int SMEM_B = B_TOTF * sizeof(float);   // 152,864 B
    cudaFuncSetAttribute(k_comm, cudaFuncAttributeMaxDynamicSharedMemorySize, SMEM_A);
    cudaFuncSetAttribute(k_main, cudaFuncAttributeMaxDynamicSharedMemorySize, SMEM_B);

    k_zero<<<1, 512>>>();
    k_comm<<<dim3(B_SIZE / TILE, NAG), 256, SMEM_A>>>(obs, W1, b1, W2, b2);
    k_pre<<<NAG, HXS>>>(Wc, bc);
    k_main<<<dim3(B_SIZE / TILE, NAG), 256, SMEM_B>>>(obs, W1, b1, W2, b2,
                                                      Wc, Wd, bd, out);
}

// round 6
// speedup vs baseline: 2.0449x; 2.0449x over previous
#include <cuda_runtime.h>
#include <cstdint>

#define B_SIZE 131072
#define NAG 8
#define HXS 64
#define ENC 128
#define ACTS 5
#define TILE 128

// scratch (device globals: no allocation allowed)
__device__ float g_comm[NAG * HXS];
__device__ float g_pre2[NAG * HXS];

// ---------------------------------------------------------------------------
// helpers
// ---------------------------------------------------------------------------
__device__ __forceinline__ uint32_t pack_bf16x2(float lo, float hi) {
    // PTX: first src -> upper half, second src -> lower half
    uint32_t r;
    asm("cvt.rn.bf16x2.f32 %0, %1, %2;" : "=r"(r) : "f"(hi), "f"(lo));
    return r;
}
// exact rn-even bf16 rounding done in integer (order-independent of cvt pack)
__device__ __forceinline__ float bf16_round(float v) {
    uint32_t b = __float_as_uint(v);
    uint32_t r = (b + 0x7fffu + ((b >> 16) & 1u)) & 0xffff0000u;
    return __uint_as_float(r);
}
__device__ __forceinline__ uint32_t split_pack(float v0, float v1, uint32_t &lop) {
    uint32_t hp = pack_bf16x2(v0, v1);
    float r0 = v0 - bf16_round(v0);
    float r1 = v1 - bf16_round(v1);
    lop = pack_bf16x2(r0, r1);
    return hp;
}
__device__ __forceinline__ void mma_bf16(float* d, uint32_t a0, uint32_t a1,
                                         uint32_t a2, uint32_t a3,
                                         uint32_t b0, uint32_t b1) {
    asm volatile(
        "mma.sync.aligned.m16n8k16.row.col.f32.bf16.bf16.f32 "
        "{%0,%1,%2,%3}, {%4,%5,%6,%7}, {%8,%9}, {%0,%1,%2,%3};"
        : "+f"(d[0]), "+f"(d[1]), "+f"(d[2]), "+f"(d[3])
        : "r"(a0), "r"(a1), "r"(a2), "r"(a3), "r"(b0), "r"(b1));
}
__device__ __forceinline__ float fast_tanh(float x) {
    float r; asm("tanh.approx.f32 %0, %1;" : "=f"(r) : "f"(x)); return r;
}

__global__ void k_zero() {
    if (threadIdx.x < NAG * HXS) g_comm[threadIdx.x] = 0.f;
}

// ---------------------------------------------------------------------------
// shared encoder: stage common inputs + bf16x3 MMA with on-the-fly h1.
// Produces acc[8][4] = (obs@W1+b1).relu @ W2  (bias b2 NOT yet added).
// ---------------------------------------------------------------------------
__device__ __forceinline__ void stage_common(
    float* sObs, float* sW1, float* sb1, float* sb2,
    uint32_t* sWH, uint32_t* sWL,
    int n, int tid, int b0,
    const float* __restrict__ obs, const float* __restrict__ W1,
    const float* __restrict__ b1, const float* __restrict__ W2,
    const float* __restrict__ b2)
{
    {
        const float4* src = (const float4*)(obs + (size_t)b0 * 16);
        float4* dst = (float4*)sObs;
        dst[tid]       = src[tid];
        dst[tid + 256] = src[tid + 256];
    }
    sW1[tid] = W1[n * 256 + tid];
    if (tid < 128) sb1[tid] = b1[n * 128 + tid];
    if (tid < 64)  sb2[tid] = b2[n * 64 + tid];
    // W2 [128][64] -> packed k-pairs, hi/lo planes [64][72]
    for (int i = tid; i < 64 * 64; i += 256) {
        int k2 = i >> 6, o = i & 63;
        float v0 = W2[n * ENC * HXS + (2 * k2) * 64 + o];
        float v1 = W2[n * ENC * HXS + (2 * k2 + 1) * 64 + o];
        uint32_t lo, hi = split_pack(v0, v1, lo);
        sWH[k2 * 72 + o] = hi;
        sWL[k2 * 72 + o] = lo;
    }
}

__device__ __forceinline__ void encoder_mma(
    const float* sObs, const float* sW1, const float* sb1,
    const uint32_t* sWH, const uint32_t* sWL,
    int n, int tid, float acc[8][4])
{
    const int w = tid >> 5, lane = tid & 31, g = lane >> 2, t = lane & 3;
    const int r0 = w * 16 + g, r1 = r0 + 8;
    const float o00 = sObs[r0 * 16 + 2 * n], o01 = sObs[r0 * 16 + 2 * n + 1];
    const float o10 = sObs[r1 * 16 + 2 * n], o11 = sObs[r1 * 16 + 2 * n + 1];

#pragma unroll
    for (int nt = 0; nt < 8; nt++)
#pragma unroll
        for (int e = 0; e < 4; e++) acc[nt][e] = 0.f;

#pragma unroll
    for (int kk = 0; kk < 8; kk++) {
        const int c0 = kk * 16 + 2 * t;   // cols c0, c0+1 (a0/a1)
        const int c8 = c0 + 8;            // cols c8, c8+1 (a2/a3)
        float wA0 = sW1[c0],     wB0 = sW1[128 + c0],     bb0 = sb1[c0];
        float wA1 = sW1[c0 + 1], wB1 = sW1[128 + c0 + 1], bb1 = sb1[c0 + 1];
        float wA8 = sW1[c8],     wB8 = sW1[128 + c8],     bb8 = sb1[c8];
        float wA9 = sW1[c8 + 1], wB9 = sW1[128 + c8 + 1], bb9 = sb1[c8 + 1];

        float v00 = fmaxf(fmaf(o00, wA0, fmaf(o01, wB0, bb0)), 0.f); // (r0,c0)
        float v01 = fmaxf(fmaf(o00, wA1, fmaf(o01, wB1, bb1)), 0.f); // (r0,c0+1)
        float v10 = fmaxf(fmaf(o10, wA0, fmaf(o11, wB0, bb0)), 0.f); // (r1,c0)
        float v11 = fmaxf(fmaf(o10, wA1, fmaf(o11, wB1, bb1)), 0.f); // (r1,c0+1)
        float v08 = fmaxf(fmaf(o00, wA8, fmaf(o01, wB8, bb8)), 0.f); // (r0,c8)
        float v09 = fmaxf(fmaf(o00, wA9, fmaf(o01, wB9, bb9)), 0.f); // (r0,c8+1)
        float v18 = fmaxf(fmaf(o10, wA8, fmaf(o11, wB8, bb8)), 0.f); // (r1,c8)
        float v19 = fmaxf(fmaf(o10, wA9, fmaf(o11, wB9, bb9)), 0.f); // (r1,c8+1)

        uint32_t a0l, a0 = split_pack(v00, v01, a0l);
        uint32_t a1l, a1 = split_pack(v10, v11, a1l);
        uint32_t a2l, a2 = split_pack(v08, v09, a2l);
        uint32_t a3l, a3 = split_pack(v18, v19, a3l);

        const int rB0 = (kk * 8 + t) * 72 + g;
        const int rB1 = (kk * 8 + t + 4) * 72 + g;
#pragma unroll
        for (int nt = 0; nt < 8; nt++) {
            uint32_t bh0 = sWH[rB0 + nt * 8];
            uint32_t bh1 = sWH[rB1 + nt * 8];
            uint32_t bl0 = sWL[rB0 + nt * 8];
            uint32_t bl1 = sWL[rB1 + nt * 8];
            mma_bf16(acc[nt], a0, a1, a2, a3, bh0, bh1);
            mma_bf16(acc[nt], a0l, a1l, a2l, a3l, bh0, bh1);
            mma_bf16(acc[nt], a0, a1, a2, a3, bl0, bl1);
        }
    }
}

// ---------------------------------------------------------------------------
// Kernel A: encoder + comm partial accumulation
// smem (floats): obs 2048 | W1 256 | b1 128 | b2 64 | pad | WH 4608 | WL 4608 |
//                sH f32 [128][68] 8704 | sC [8][132] 1056
// ---------------------------------------------------------------------------
#define C_OBS 0
#define C_W1  2048
#define C_B1  2304
#define C_B2  2432
#define C_WH  2496
#define C_WL  7104
#define C_SH  11712
#define C_SC  20416
#define C_TOT 21472

__global__ __launch_bounds__(256) void k_comm(
    const float* __restrict__ obs, const float* __restrict__ W1,
    const float* __restrict__ b1, const float* __restrict__ W2,
    const float* __restrict__ b2)
{
    extern __shared__ float sm[];
    float* sObs = sm + C_OBS;
    float* sW1  = sm + C_W1;
    float* sb1  = sm + C_B1;
    float* sb2  = sm + C_B2;
    uint32_t* sWH = (uint32_t*)(sm + C_WH);
    uint32_t* sWL = (uint32_t*)(sm + C_WL);
    float* sH = sm + C_SH;   // stride 68
    float* sC = sm + C_SC;   // stride 132

    const int n   = blockIdx.y;
    const int tid = threadIdx.x;
    const int b0  = blockIdx.x * TILE;

    stage_common(sObs, sW1, sb1, sb2, sWH, sWL, n, tid, b0, obs, W1, b1, W2, b2);
    __syncthreads();

    float acc[8][4];
    encoder_mma(sObs, sW1, sb1, sWH, sWL, n, tid, acc);

    // epilogue: h = relu(acc + b2) -> sH fp32
    const int w = tid >> 5, lane = tid & 31, g = lane >> 2, t = lane & 3;
    const int r0 = w * 16 + g, r1 = r0 + 8;
#pragma unroll
    for (int nt = 0; nt < 8; nt++) {
        int c0 = nt * 8 + 2 * t;
        float p0 = sb2[c0], p1 = sb2[c0 + 1];
        sH[r0 * 68 + c0]     = fmaxf(acc[nt][0] + p0, 0.f);
        sH[r0 * 68 + c0 + 1] = fmaxf(acc[nt][1] + p1, 0.f);
        sH[r1 * 68 + c0]     = fmaxf(acc[nt][2] + p0, 0.f);
        sH[r1 * 68 + c0 + 1] = fmaxf(acc[nt][3] + p1, 0.f);
    }

    // comm coefficients: coef_i = mask[i][n] / J[i]
    if (tid < 128) {
        float px[NAG], py[NAG];
#pragma unroll
        for (int j = 0; j < NAG; j++) {
            px[j] = sObs[tid * 16 + 2 * j] * 2.0f;       // GRID[0]-1
            py[j] = sObs[tid * 16 + 2 * j + 1] * 6.0f;   // GRID[1]-1
        }
#pragma unroll
        for (int i = 0; i < NAG; i++) {
            float J = 0.f, mn = 0.f;
#pragma unroll
            for (int j = 0; j < NAG; j++) {
                float d = fabsf(px[i] - px[j]) + fabsf(py[i] - py[j]);
                bool msk = (d > 0.f) && (d < 2.0f);
                J += msk ? 1.f : 0.f;
                if (j == n) mn = msk ? 1.f : 0.f;
            }
            if (J <= 0.f) J = 1.f;
            sC[i * 132 + tid] = mn / J;
        }
    }
    __syncthreads();

    // per-block 8x64 reduction
    const int o = tid & 63, i0 = tid >> 6;
    float s0 = 0.f, s1 = 0.f;
#pragma unroll 4
    for (int bb = 0; bb < TILE; bb++) {
        float hv = sH[bb * 68 + o];
        s0 = fmaf(sC[i0 * 132 + bb], hv, s0);
        s1 = fmaf(sC[(i0 + 4) * 132 + bb], hv, s1);
    }
    atomicAdd(&g_comm[i0 * 64 + o], s0);
    atomicAdd(&g_comm[(i0 + 4) * 64 + o], s1);
}

// pre2[n][o] = bc[n][o] + sum_h comm[n][h] * Wc[n][HX+h][o]
__global__ void k_pre(const float* __restrict__ Wc, const float* __restrict__ bc) {
    const int n = blockIdx.x, o = threadIdx.x;
    float s = bc[n * HXS + o];
#pragma unroll 8
    for (int h = 0; h < HXS; h++)
        s = fmaf(g_comm[n * HXS + h], Wc[n * 2 * HXS * HXS + (HXS + h) * HXS + o], s);
    g_pre2[n * HXS + o] = s;
}

// ---------------------------------------------------------------------------
// Kernel B: encoder (recompute) + fused decoder
// smem (floats): obs 2048 | W1 256 | b1 128 | b2 64 | pre2 64 | bd 8 | Wd 320 |
//   pad | WH 4608 | WL 4608 | CH 2304 | CL 2304 | Hh 4608 | Hl 4608
// sH2 (f32, stride 65) reuses the WH/WL region post-encoder.
// ---------------------------------------------------------------------------
#define M_OBS 0
#define M_W1  2048
#define M_B1  2304
#define M_B2  2432
#define M_P   2496
#define M_BD  2560
#define M_WD  2576
#define M_WH  2944
#define M_WL  7552
#define M_CH  12160
#define M_CL  14464
#define M_HH  16768
#define M_HL  21376
#define M_TOT 25984

__global__ __launch_bounds__(256) void k_main(
    const float* __restrict__ obs, const float* __restrict__ W1,
    const float* __restrict__ b1, const float* __restrict__ W2,
    const float* __restrict__ b2, const float* __restrict__ Wc,
    const float* __restrict__ Wd, const float* __restrict__ bd,
    float* __restrict__ out)
{
    extern __shared__ float sm[];
    float* sObs = sm + M_OBS;
    float* sW1  = sm + M_W1;
    float* sb1  = sm + M_B1;
    float* sb2  = sm + M_B2;
    float* sP   = sm + M_P;
    float* sbd  = sm + M_BD;
    float* sWd  = sm + M_WD;
    uint32_t* sWH = (uint32_t*)(sm + M_WH);
    uint32_t* sWL = (uint32_t*)(sm + M_WL);
    uint32_t* sCH = (uint32_t*)(sm + M_CH);
    uint32_t* sCL = (uint32_t*)(sm + M_CL);
    uint32_t* sHh = (uint32_t*)(sm + M_HH);
    uint32_t* sHl = (uint32_t*)(sm + M_HL);
    float* sH2 = sm + M_WH;   // f32, stride 65, reused post-encoder

    const int n   = blockIdx.y;
    const int tid = threadIdx.x;
    const int b0  = blockIdx.x * TILE;

    stage_common(sObs, sW1, sb1, sb2, sWH, sWL, n, tid, b0, obs, W1, b1, W2, b2);
    // Wc lower half [64][64] -> packed planes [32][72]
    for (int i = tid; i < 32 * 64; i += 256) {
        int k2 = i >> 6, o = i & 63;
        float v0 = Wc[n * 2 * HXS * HXS + (2 * k2) * 64 + o];
        float v1 = Wc[n * 2 * HXS * HXS + (2 * k2 + 1) * 64 + o];
        uint32_t lo, hi = split_pack(v0, v1, lo);
        sCH[k2 * 72 + o] = hi;
        sCL[k2 * 72 + o] = lo;
    }
    for (int i = tid; i < HXS * ACTS; i += 256) sWd[i] = Wd[n * HXS * ACTS + i];
    if (tid < 64) sP[tid] = g_pre2[n * 64 + tid];
    if (tid < 5)  sbd[tid] = bd[n * 5 + tid];
    __syncthreads();

    float acc[8][4];
    encoder_mma(sObs, sW1, sb1, sWH, sWL, n, tid, acc);

    const int w = tid >> 5, lane = tid & 31, g = lane >> 2, t = lane & 3;
    const int r0 = w * 16 + g, r1 = r0 + 8;

    // epilogue: h = relu(acc + b2) -> packed hi/lo planes (warp-private rows)
#pragma unroll
    for (int nt = 0; nt < 8; nt++) {
        int c0 = nt * 8 + 2 * t;
        float p0 = sb2[c0], p1 = sb2[c0 + 1];
        float v00 = fmaxf(acc[nt][0] + p0, 0.f);
        float v01 = fmaxf(acc[nt][1] + p1, 0.f);
        float v10 = fmaxf(acc[nt][2] + p0, 0.f);
        float v11 = fmaxf(acc[nt][3] + p1, 0.f);
        uint32_t l0, h0 = split_pack(v00, v01, l0);
        uint32_t l1, h1 = split_pack(v10, v11, l1);
        sHh[r0 * 36 + nt * 4 + t] = h0;  sHl[r0 * 36 + nt * 4 + t] = l0;
        sHh[r1 * 36 + nt * 4 + t] = h1;  sHl[r1 * 36 + nt * 4 + t] = l1;
    }
    __syncwarp();

    // decoder MMA: [128 x 64] @ [64 x 64] bf16x3
    float acc2[8][4];
#pragma unroll
    for (int nt = 0; nt < 8; nt++)
#pragma unroll
        for (int e = 0; e < 4; e++) acc2[nt][e] = 0.f;

#pragma unroll
    for (int kk = 0; kk < 4; kk++) {
        uint32_t a0  = sHh[r0 * 36 + kk * 8 + t];
        uint32_t a1  = sHh[r1 * 36 + kk * 8 + t];
        uint32_t a2  = sHh[r0 * 36 + kk * 8 + t + 4];
        uint32_t a3  = sHh[r1 * 36 + kk * 8 + t + 4];
        uint32_t a0l = sHl[r0 * 36 + kk * 8 + t];
        uint32_t a1l = sHl[r1 * 36 + kk * 8 + t];
        uint32_t a2l = sHl[r0 * 36 + kk * 8 + t + 4];
        uint32_t a3l = sHl[r1 * 36 + kk * 8 + t + 4];
        const int rB0 = (kk * 8 + t) * 72 + g;
        const int rB1 = (kk * 8 + t + 4) * 72 + g;
#pragma unroll
        for (int nt = 0; nt < 8; nt++) {
            uint32_t bh0 = sCH[rB0 + nt * 8];
            uint32_t bh1 = sCH[rB1 + nt * 8];
            uint32_t bl0 = sCL[rB0 + nt * 8];
            uint32_t bl1 = sCL[rB1 + nt * 8];
            mma_bf16(acc2[nt], a0, a1, a2, a3, bh0, bh1);
            mma_bf16(acc2[nt], a0l, a1l, a2l, a3l, bh0, bh1);
            mma_bf16(acc2[nt], a0, a1, a2, a3, bl0, bl1);
        }
    }
    __syncthreads();   // everyone done reading WH/WL region before overwrite

    // h2 = tanh(acc2 + pre2) -> sH2 (stride 65, over old weight planes)
#pragma unroll
    for (int nt = 0; nt < 8; nt++) {
        int c0 = nt * 8 + 2 * t;
        float p0 = sP[c0], p1 = sP[c0 + 1];
        sH2[r0 * 65 + c0]     = fast_tanh(acc2[nt][0] + p0);
        sH2[r0 * 65 + c0 + 1] = fast_tanh(acc2[nt][1] + p1);
        sH2[r1 * 65 + c0]     = fast_tanh(acc2[nt][2] + p0);
        sH2[r1 * 65 + c0 + 1] = fast_tanh(acc2[nt][3] + p1);
    }
    __syncthreads();

    // q = h2 @ Wd + bd, one batch row per thread (tid < 128)
    if (tid < 128) {
        float q0 = sbd[0], q1 = sbd[1], q2 = sbd[2], q3 = sbd[3], q4 = sbd[4];
        const float* hr = sH2 + tid * 65;
#pragma unroll
        for (int j = 0; j < 64; j++) {
            float hv = hr[j];
            const float* wd = sWd + j * 5;
            q0 = fmaf(hv, wd[0], q0);
            q1 = fmaf(hv, wd[1], q1);
            q2 = fmaf(hv, wd[2], q2);
            q3 = fmaf(hv, wd[3], q3);
            q4 = fmaf(hv, wd[4], q4);
        }
        float* o = out + ((size_t)(b0 + tid) * NAG + n) * ACTS;
        o[0] = q0; o[1] = q1; o[2] = q2; o[3] = q3; o[4] = q4;
    }
}

extern "C" void kernel_launch(void* const* d_in, const int* in_sizes, int n_in,
                              void* d_out, int out_size)
{
    const float* obs = (const float*)d_in[0];
    const float* W1  = (const float*)d_in[1];
    const float* b1  = (const float*)d_in[2];
    const float* W2  = (const float*)d_in[3];
    const float* b2  = (const float*)d_in[4];
    const float* Wc  = (const float*)d_in[5];
    const float* bc  = (const float*)d_in[6];
    const float* Wd  = (const float*)d_in[7];
    const float* bd  = (const float*)d_in[8];
    float* out = (float*)d_out;

    const int SMEM_C = C_TOT * sizeof(float);   //  85,888 B
    const int SMEM_M = M_TOT * sizeof(float);   // 103,936 B
    cudaFuncSetAttribute(k_comm, cudaFuncAttributeMaxDynamicSharedMemorySize, SMEM_C);
    cudaFuncSetAttribute(k_main, cudaFuncAttributeMaxDynamicSharedMemorySize, SMEM_M);

    k_zero<<<1, 512>>>();
    k_comm<<<dim3(B_SIZE / TILE, NAG), 256, SMEM_C>>>(obs, W1, b1, W2, b2);
    k_pre<<<NAG, HXS>>>(Wc, bc);
    k_main<<<dim3(B_SIZE / TILE, NAG), 256, SMEM_M>>>(obs, W1, b1, W2, b2,
                                                      Wc, Wd, bd, out);
}

// round 7
// speedup vs baseline: 3.6676x; 1.7936x over previous
#include <cuda_runtime.h>
#include <cstdint>

#define B_SIZE 131072
#define NAG 8
#define HXS 64
#define ENC 128
#define ACTS 5
#define TILE 128
#define NBLK (B_SIZE / TILE)   // 1024

// scratch (device globals: no allocation allowed)
__device__ float g_comm[NAG * HXS];
__device__ float g_pre2[NAG * HXS];
// packed h in per-thread fragment order: per CTA 2048 uint4
// (q=0..3 hi planes, q=4..7 lo planes; index q*256+tid)
__device__ uint4 g_hpk[(size_t)NBLK * NAG * 2048];   // 256 MiB

// ---------------------------------------------------------------------------
// helpers
// ---------------------------------------------------------------------------
__device__ __forceinline__ uint32_t pack_bf16x2(float lo, float hi) {
    // result: lo -> lower 16 bits, hi -> upper 16 bits
    uint32_t r;
    asm("cvt.rn.bf16x2.f32 %0, %1, %2;" : "=r"(r) : "f"(hi), "f"(lo));
    return r;
}
// split v0,v1 into packed bf16 hi + residual lo planes; residual derived
// from the packed bits (exact, cheap)
__device__ __forceinline__ uint32_t split_pack(float v0, float v1, uint32_t &lop) {
    uint32_t hp = pack_bf16x2(v0, v1);
    float r0 = v0 - __uint_as_float(hp << 16);
    float r1 = v1 - __uint_as_float(hp & 0xffff0000u);
    lop = pack_bf16x2(r0, r1);
    return hp;
}
__device__ __forceinline__ void mma_bf16(float* d, uint32_t a0, uint32_t a1,
                                         uint32_t a2, uint32_t a3,
                                         uint32_t b0, uint32_t b1) {
    asm volatile(
        "mma.sync.aligned.m16n8k16.row.col.f32.bf16.bf16.f32 "
        "{%0,%1,%2,%3}, {%4,%5,%6,%7}, {%8,%9}, {%0,%1,%2,%3};"
        : "+f"(d[0]), "+f"(d[1]), "+f"(d[2]), "+f"(d[3])
        : "r"(a0), "r"(a1), "r"(a2), "r"(a3), "r"(b0), "r"(b1));
}
__device__ __forceinline__ float fast_tanh(float x) {
    float r; asm("tanh.approx.f32 %0, %1;" : "=f"(r) : "f"(x)); return r;
}

__global__ void k_zero() {
    if (threadIdx.x < NAG * HXS) g_comm[threadIdx.x] = 0.f;
}

// ---------------------------------------------------------------------------
// encoder helpers (bf16x3, on-the-fly h1)
// ---------------------------------------------------------------------------
__device__ __forceinline__ void stage_common(
    float* sObs, float* sW1, float* sb1, float* sb2,
    uint32_t* sWH, uint32_t* sWL,
    int n, int tid, int b0,
    const float* __restrict__ obs, const float* __restrict__ W1,
    const float* __restrict__ b1, const float* __restrict__ W2,
    const float* __restrict__ b2)
{
    {
        const float4* src = (const float4*)(obs + (size_t)b0 * 16);
        float4* dst = (float4*)sObs;
        dst[tid]       = src[tid];
        dst[tid + 256] = src[tid + 256];
    }
    sW1[tid] = W1[n * 256 + tid];
    if (tid < 128) sb1[tid] = b1[n * 128 + tid];
    if (tid < 64)  sb2[tid] = b2[n * 64 + tid];
    // W2 [128][64] -> packed k-pairs, hi/lo planes [64][72]
    for (int i = tid; i < 64 * 64; i += 256) {
        int k2 = i >> 6, o = i & 63;
        float v0 = W2[n * ENC * HXS + (2 * k2) * 64 + o];
        float v1 = W2[n * ENC * HXS + (2 * k2 + 1) * 64 + o];
        uint32_t lo, hi = split_pack(v0, v1, lo);
        sWH[k2 * 72 + o] = hi;
        sWL[k2 * 72 + o] = lo;
    }
}

__device__ __forceinline__ void encoder_mma(
    const float* sObs, const float* sW1, const float* sb1,
    const uint32_t* sWH, const uint32_t* sWL,
    int n, int tid, float acc[8][4])
{
    const int w = tid >> 5, lane = tid & 31, g = lane >> 2, t = lane & 3;
    const int r0 = w * 16 + g, r1 = r0 + 8;
    const float o00 = sObs[r0 * 16 + 2 * n], o01 = sObs[r0 * 16 + 2 * n + 1];
    const float o10 = sObs[r1 * 16 + 2 * n], o11 = sObs[r1 * 16 + 2 * n + 1];

#pragma unroll
    for (int nt = 0; nt < 8; nt++)
#pragma unroll
        for (int e = 0; e < 4; e++) acc[nt][e] = 0.f;

#pragma unroll
    for (int kk = 0; kk < 8; kk++) {
        const int c0 = kk * 16 + 2 * t;
        const int c8 = c0 + 8;
        float wA0 = sW1[c0],     wB0 = sW1[128 + c0],     bb0 = sb1[c0];
        float wA1 = sW1[c0 + 1], wB1 = sW1[128 + c0 + 1], bb1 = sb1[c0 + 1];
        float wA8 = sW1[c8],     wB8 = sW1[128 + c8],     bb8 = sb1[c8];
        float wA9 = sW1[c8 + 1], wB9 = sW1[128 + c8 + 1], bb9 = sb1[c8 + 1];

        float v00 = fmaxf(fmaf(o00, wA0, fmaf(o01, wB0, bb0)), 0.f);
        float v01 = fmaxf(fmaf(o00, wA1, fmaf(o01, wB1, bb1)), 0.f);
        float v10 = fmaxf(fmaf(o10, wA0, fmaf(o11, wB0, bb0)), 0.f);
        float v11 = fmaxf(fmaf(o10, wA1, fmaf(o11, wB1, bb1)), 0.f);
        float v08 = fmaxf(fmaf(o00, wA8, fmaf(o01, wB8, bb8)), 0.f);
        float v09 = fmaxf(fmaf(o00, wA9, fmaf(o01, wB9, bb9)), 0.f);
        float v18 = fmaxf(fmaf(o10, wA8, fmaf(o11, wB8, bb8)), 0.f);
        float v19 = fmaxf(fmaf(o10, wA9, fmaf(o11, wB9, bb9)), 0.f);

        uint32_t a0l, a0 = split_pack(v00, v01, a0l);
        uint32_t a1l, a1 = split_pack(v10, v11, a1l);
        uint32_t a2l, a2 = split_pack(v08, v09, a2l);
        uint32_t a3l, a3 = split_pack(v18, v19, a3l);

        const int rB0 = (kk * 8 + t) * 72 + g;
        const int rB1 = (kk * 8 + t + 4) * 72 + g;
#pragma unroll
        for (int nt = 0; nt < 8; nt++) {
            uint32_t bh0 = sWH[rB0 + nt * 8];
            uint32_t bh1 = sWH[rB1 + nt * 8];
            uint32_t bl0 = sWL[rB0 + nt * 8];
            uint32_t bl1 = sWL[rB1 + nt * 8];
            mma_bf16(acc[nt], a0, a1, a2, a3, bh0, bh1);
            mma_bf16(acc[nt], a0l, a1l, a2l, a3l, bh0, bh1);
            mma_bf16(acc[nt], a0, a1, a2, a3, bl0, bl1);
        }
    }
}

// ---------------------------------------------------------------------------
// Kernel A: encoder + comm partials + packed h store (fragment order)
// smem (floats): obs 2048 | W1 256 | b1 128 | b2 64 | WH 4608 | WL 4608 |
//                HP (u32 [128][36]) 4608 | sC [8][132] 1056   = 17376 (69.5 KB)
// ---------------------------------------------------------------------------
#define C_OBS 0
#define C_W1  2048
#define C_B1  2304
#define C_B2  2432
#define C_WH  2496
#define C_WL  7104
#define C_HP  11712
#define C_SC  16320
#define C_TOT 17376

__global__ __launch_bounds__(256) void k_comm(
    const float* __restrict__ obs, const float* __restrict__ W1,
    const float* __restrict__ b1, const float* __restrict__ W2,
    const float* __restrict__ b2)
{
    extern __shared__ float sm[];
    float* sObs = sm + C_OBS;
    float* sW1  = sm + C_W1;
    float* sb1  = sm + C_B1;
    float* sb2  = sm + C_B2;
    uint32_t* sWH = (uint32_t*)(sm + C_WH);
    uint32_t* sWL = (uint32_t*)(sm + C_WL);
    uint32_t* sHp = (uint32_t*)(sm + C_HP);   // [128][36] packed bf16 pairs
    float* sC = sm + C_SC;                    // [8][132]

    const int n   = blockIdx.y;
    const int tid = threadIdx.x;
    const int b0  = blockIdx.x * TILE;

    stage_common(sObs, sW1, sb1, sb2, sWH, sWL, n, tid, b0, obs, W1, b1, W2, b2);
    __syncthreads();

    float acc[8][4];
    encoder_mma(sObs, sW1, sb1, sWH, sWL, n, tid, acc);

    const int w = tid >> 5, lane = tid & 31, g = lane >> 2, t = lane & 3;
    const int r0 = w * 16 + g, r1 = r0 + 8;

    // epilogue: h = relu(acc + b2); write smem packed tile + global fragment store
    const int ctaL = blockIdx.y * gridDim.x + blockIdx.x;
    uint4* gp = g_hpk + (size_t)ctaL * 2048;
#pragma unroll
    for (int kk = 0; kk < 4; kk++) {
        uint32_t hh[4], ll[4];
#pragma unroll
        for (int s = 0; s < 2; s++) {
            int nt = 2 * kk + s;
            int c0 = nt * 8 + 2 * t;
            float p0 = sb2[c0], p1 = sb2[c0 + 1];
            float v00 = fmaxf(acc[nt][0] + p0, 0.f);
            float v01 = fmaxf(acc[nt][1] + p1, 0.f);
            float v10 = fmaxf(acc[nt][2] + p0, 0.f);
            float v11 = fmaxf(acc[nt][3] + p1, 0.f);
            uint32_t l0, h0 = split_pack(v00, v01, l0);
            uint32_t l1, h1 = split_pack(v10, v11, l1);
            sHp[r0 * 36 + nt * 4 + t] = h0;
            sHp[r1 * 36 + nt * 4 + t] = h1;
            hh[2 * s] = h0; hh[2 * s + 1] = h1;
            ll[2 * s] = l0; ll[2 * s + 1] = l1;
        }
        gp[kk * 256 + tid]       = make_uint4(hh[0], hh[1], hh[2], hh[3]);
        gp[(4 + kk) * 256 + tid] = make_uint4(ll[0], ll[1], ll[2], ll[3]);
    }

    // comm coefficients: coef_i = mask[i][n] / J[i]
    if (tid < 128) {
        float px[NAG], py[NAG];
#pragma unroll
        for (int j = 0; j < NAG; j++) {
            px[j] = sObs[tid * 16 + 2 * j] * 2.0f;       // GRID[0]-1
            py[j] = sObs[tid * 16 + 2 * j + 1] * 6.0f;   // GRID[1]-1
        }
#pragma unroll
        for (int i = 0; i < NAG; i++) {
            float J = 0.f, mn = 0.f;
#pragma unroll
            for (int j = 0; j < NAG; j++) {
                float d = fabsf(px[i] - px[j]) + fabsf(py[i] - py[j]);
                bool msk = (d > 0.f) && (d < 2.0f);
                J += msk ? 1.f : 0.f;
                if (j == n) mn = msk ? 1.f : 0.f;
            }
            if (J <= 0.f) J = 1.f;
            sC[i * 132 + tid] = mn / J;
        }
    }
    __syncthreads();

    // per-block 8x64 reduction off the packed (hi bf16) tile
    const int o = tid & 63, i0 = tid >> 6;
    const bool odd = (o & 1);
    float s0 = 0.f, s1 = 0.f;
#pragma unroll 4
    for (int bb = 0; bb < TILE; bb++) {
        uint32_t u = sHp[bb * 36 + (o >> 1)];
        float hv = __uint_as_float(odd ? (u & 0xffff0000u) : (u << 16));
        s0 = fmaf(sC[i0 * 132 + bb], hv, s0);
        s1 = fmaf(sC[(i0 + 4) * 132 + bb], hv, s1);
    }
    atomicAdd(&g_comm[i0 * 64 + o], s0);
    atomicAdd(&g_comm[(i0 + 4) * 64 + o], s1);
}

// pre2[n][o] = bc[n][o] + sum_h comm[n][h] * Wc[n][HX+h][o]
__global__ void k_pre(const float* __restrict__ Wc, const float* __restrict__ bc) {
    const int n = blockIdx.x, o = threadIdx.x;
    float s = bc[n * HXS + o];
#pragma unroll 8
    for (int h = 0; h < HXS; h++)
        s = fmaf(g_comm[n * HXS + h], Wc[n * 2 * HXS * HXS + (HXS + h) * HXS + o], s);
    g_pre2[n * HXS + o] = s;
}

// ---------------------------------------------------------------------------
// Kernel B: decoder only — h fragments loaded straight from g_hpk.
// smem (floats): CH 2304 | CL 2304 | Wd 320 | pre2 64 | bd 8  = 5000 (20 KB)
// ---------------------------------------------------------------------------
#define D_CH  0
#define D_CL  2304
#define D_WD  4608
#define D_P   4928
#define D_BD  4992
#define D_TOT 5000

__global__ __launch_bounds__(256) void k_main(
    const float* __restrict__ Wc, const float* __restrict__ Wd,
    const float* __restrict__ bd, float* __restrict__ out)
{
    extern __shared__ float sm[];
    uint32_t* sCH = (uint32_t*)(sm + D_CH);
    uint32_t* sCL = (uint32_t*)(sm + D_CL);
    float* sWd = sm + D_WD;
    float* sP  = sm + D_P;
    float* sbd = sm + D_BD;

    const int n   = blockIdx.y;
    const int tid = threadIdx.x;
    const int b0  = blockIdx.x * TILE;

    // Wc lower half [64][64] -> packed planes [32][72]
    for (int i = tid; i < 32 * 64; i += 256) {
        int k2 = i >> 6, o = i & 63;
        float v0 = Wc[n * 2 * HXS * HXS + (2 * k2) * 64 + o];
        float v1 = Wc[n * 2 * HXS * HXS + (2 * k2 + 1) * 64 + o];
        uint32_t lo, hi = split_pack(v0, v1, lo);
        sCH[k2 * 72 + o] = hi;
        sCL[k2 * 72 + o] = lo;
    }
    for (int i = tid; i < HXS * ACTS; i += 256) sWd[i] = Wd[n * HXS * ACTS + i];
    if (tid < 64) sP[tid] = g_pre2[n * 64 + tid];
    if (tid < 5)  sbd[tid] = bd[n * 5 + tid];
    __syncthreads();

    const int w = tid >> 5, lane = tid & 31, g = lane >> 2, t = lane & 3;
    const int r0 = w * 16 + g, r1 = r0 + 8;
    const int ctaL = blockIdx.y * gridDim.x + blockIdx.x;
    const uint4* gp = g_hpk + (size_t)ctaL * 2048;

    float acc2[8][4];
#pragma unroll
    for (int nt = 0; nt < 8; nt++)
#pragma unroll
        for (int e = 0; e < 4; e++) acc2[nt][e] = 0.f;

#pragma unroll
    for (int kk = 0; kk < 4; kk++) {
        uint4 H = gp[kk * 256 + tid];        // a0..a3 hi (fragment order)
        uint4 L = gp[(4 + kk) * 256 + tid];  // a0..a3 lo
        const int rB0 = (kk * 8 + t) * 72 + g;
        const int rB1 = (kk * 8 + t + 4) * 72 + g;
#pragma unroll
        for (int nt = 0; nt < 8; nt++) {
            uint32_t bh0 = sCH[rB0 + nt * 8];
            uint32_t bh1 = sCH[rB1 + nt * 8];
            uint32_t bl0 = sCL[rB0 + nt * 8];
            uint32_t bl1 = sCL[rB1 + nt * 8];
            mma_bf16(acc2[nt], H.x, H.y, H.z, H.w, bh0, bh1);
            mma_bf16(acc2[nt], L.x, L.y, L.z, L.w, bh0, bh1);
            mma_bf16(acc2[nt], H.x, H.y, H.z, H.w, bl0, bl1);
        }
    }

    // h2 = tanh(acc2 + pre2) and q-partials, all in registers
    float q0[ACTS], q1[ACTS];
#pragma unroll
    for (int a = 0; a < ACTS; a++) { q0[a] = 0.f; q1[a] = 0.f; }
#pragma unroll
    for (int nt = 0; nt < 8; nt++) {
        int c0 = nt * 8 + 2 * t;
        float p0 = sP[c0], p1 = sP[c0 + 1];
        float t00 = fast_tanh(acc2[nt][0] + p0);
        float t01 = fast_tanh(acc2[nt][1] + p1);
        float t10 = fast_tanh(acc2[nt][2] + p0);
        float t11 = fast_tanh(acc2[nt][3] + p1);
        const float* wd0 = sWd + c0 * 5;
        const float* wd1 = sWd + (c0 + 1) * 5;
#pragma unroll
        for (int a = 0; a < ACTS; a++) {
            q0[a] = fmaf(t00, wd0[a], fmaf(t01, wd1[a], q0[a]));
            q1[a] = fmaf(t10, wd0[a], fmaf(t11, wd1[a], q1[a]));
        }
    }
    // reduce across the 4 t-lanes (lane bits 0,1)
#pragma unroll
    for (int a = 0; a < ACTS; a++) {
        q0[a] += __shfl_xor_sync(0xffffffffu, q0[a], 1);
        q0[a] += __shfl_xor_sync(0xffffffffu, q0[a], 2);
        q1[a] += __shfl_xor_sync(0xffffffffu, q1[a], 1);
        q1[a] += __shfl_xor_sync(0xffffffffu, q1[a], 2);
    }
    if (t == 0) {
        float* o0 = out + ((size_t)(b0 + r0) * NAG + n) * ACTS;
        float* o1 = out + ((size_t)(b0 + r1) * NAG + n) * ACTS;
#pragma unroll
        for (int a = 0; a < ACTS; a++) {
            o0[a] = q0[a] + sbd[a];
            o1[a] = q1[a] + sbd[a];
        }
    }
}

extern "C" void kernel_launch(void* const* d_in, const int* in_sizes, int n_in,
                              void* d_out, int out_size)
{
    const float* obs = (const float*)d_in[0];
    const float* W1  = (const float*)d_in[1];
    const float* b1  = (const float*)d_in[2];
    const float* W2  = (const float*)d_in[3];
    const float* b2  = (const float*)d_in[4];
    const float* Wc  = (const float*)d_in[5];
    const float* bc  = (const float*)d_in[6];
    const float* Wd  = (const float*)d_in[7];
    const float* bd  = (const float*)d_in[8];
    float* out = (float*)d_out;

    const int SMEM_C = C_TOT * sizeof(float);   // 69,504 B -> 3 CTAs/SM
    const int SMEM_D = D_TOT * sizeof(float);   // 20,000 B
    cudaFuncSetAttribute(k_comm, cudaFuncAttributeMaxDynamicSharedMemorySize, SMEM_C);
    cudaFuncSetAttribute(k_main, cudaFuncAttributeMaxDynamicSharedMemorySize, SMEM_D);

    k_zero<<<1, 512>>>();
    k_comm<<<dim3(NBLK, NAG), 256, SMEM_C>>>(obs, W1, b1, W2, b2);
    k_pre<<<NAG, HXS>>>(Wc, bc);
    k_main<<<dim3(NBLK, NAG), 256, SMEM_D>>>(Wc, Wd, bd, out);
}